// round 16
// baseline (speedup 1.0000x reference)
#include <cuda_runtime.h>
#include <cuda_bf16.h>

#define TT 256
#define SIGMA_INV (1.0f / 100.0f)
#define BLOCKS 512
#define THREADS 256
#define WPB 8                  // warps per block

// Scratch: device globals (allocation-free rule). Zero at module load; the
// LAST block re-zeros after consuming, so every graph replay sees clean state.
__device__ float        gS[TT];   // S[t] = sum_j ev_j [y_j > t] exp(F1[j,t]/s)
__device__ float        gH[TT];   // H[t] = sum_{i: y_i = t} ev_i exp(-A_i/s)
__device__ double       gL1;
__device__ unsigned int gCount;

// exp(x) for |x| <= 0.009 : cubic Taylor, rel err < 3e-10
__device__ __forceinline__ float exp_small(float x) {
    return fmaf(x, fmaf(x, fmaf(x, 0.16666667f, 0.5f), 1.0f), 1.0f);
}

__global__ void __launch_bounds__(THREADS, 4)
surv_fused(const float* __restrict__ yp,
           const void*  __restrict__ yv,
           const float* __restrict__ status,
           int N,
           float* __restrict__ out) {
    const int t    = threadIdx.x;
    const int lane = t & 31;
    const int w    = t >> 5;
    const int gw   = blockIdx.x * WPB + w;
    const int W    = gridDim.x * WPB;       // 4096 warps -> exactly 2 rows each
    const int* y32 = (const int*)yv;

    // ---- issue ALL independent global loads up front ----
    const int det = (2 * lane + 1 < N) ? y32[2 * lane + 1] : 0;

    const int ja = gw, jb = gw + W;          // this warp's two rows
    float4 xa0, xa1, xb0, xb1;
    if (ja < N) {
        const float* r = yp + (size_t)ja * TT + lane * 8;
        xa0 = *(const float4*)(r); xa1 = *(const float4*)(r + 4);
    }
    if (jb < N) {
        const float* r = yp + (size_t)jb * TT + lane * 8;
        xb0 = *(const float4*)(r); xb1 = *(const float4*)(r + 4);
    }

    // speculative metadata: int32 candidate (word j, in-bounds always) and
    // int64 candidate (word 2j, issued when 2j < N — in-bounds under both
    // width interpretations). Status loads are width-independent.
    int y32a = 0, y32b = 0, y64a = 0, y64b = 0;
    float sta = 0.0f, stb = 0.0f;
    if (lane == 0) {
        if (ja < N) {
            y32a = y32[ja];
            if (2 * ja < N) y64a = y32[2 * ja];
            sta = status[ja];
        }
        if (jb < N) {
            y32b = y32[jb];
            if (2 * jb < N) y64b = y32[2 * jb];
            stb = status[jb];
        }
    }

    // width detect (int64 LE: odd 32-bit words all zero since 0 <= y < 256)
    const bool is64 = (__ballot_sync(0xffffffffu, det != 0) == 0u);

    int pk = 0;
    if (lane == 0) {
        if (ja < N) {
            int ya = is64 ? ((2 * ja < N) ? y64a : y32[2 * ja]) : y32a;
            pk |= ya | ((sta > 0.5f) ? 256 : 0);
        }
        if (jb < N) {
            int yb = is64 ? ((2 * jb < N) ? y64b : y32[2 * jb]) : y32b;
            pk |= (yb << 16) | ((stb > 0.5f) ? (1 << 24) : 0);
        }
    }

    __shared__ float sH[TT];
    __shared__ float sL1;
    sH[t] = 0.0f;
    if (t == 0) sL1 = 0.0f;
    __syncthreads();                          // visible before loop atomics

    pk = __shfl_sync(0xffffffffu, pk, 0);     // one broadcast for both rows
    const int  ya  = pk & 255;
    const bool eva = (pk & 256) != 0;
    const int  yb  = (pk >> 16) & 255;
    const bool evb = (pk & (1 << 24)) != 0;

    float acc[8];
    #pragma unroll
    for (int k = 0; k < 8; k++) acc[k] = 0.0f;

    // ---- local inclusive prefixes (independent chains) ----
    float sa[8], sb[8];
    if (ja < N) {
        sa[0] = xa0.x; sa[1] = sa[0] + xa0.y; sa[2] = sa[1] + xa0.z;
        sa[3] = sa[2] + xa0.w; sa[4] = sa[3] + xa1.x; sa[5] = sa[4] + xa1.y;
        sa[6] = sa[5] + xa1.z; sa[7] = sa[6] + xa1.w;
    }
    if (jb < N) {
        sb[0] = xb0.x; sb[1] = sb[0] + xb0.y; sb[2] = sb[1] + xb0.z;
        sb[3] = sb[2] + xb0.w; sb[4] = sb[3] + xb1.x; sb[5] = sb[4] + xb1.y;
        sb[6] = sb[5] + xb1.z; sb[7] = sb[6] + xb1.w;
    }

    // ---- interleaved warp scans (latencies overlap) ----
    float ta = (ja < N) ? sa[7] : 0.0f;
    float tb = (jb < N) ? sb[7] : 0.0f;
    float sca = ta, scb = tb;
    #pragma unroll
    for (int o = 1; o < 32; o <<= 1) {
        float na = __shfl_up_sync(0xffffffffu, sca, o);
        float nb = __shfl_up_sync(0xffffffffu, scb, o);
        if (lane >= o) { sca += na; scb += nb; }
    }
    const float offa = sca - ta;
    const float offb = scb - tb;
    const int base = lane * 8;

    // ---- row A ----
    if (ja < N) {
        if (lane == (ya >> 3)) {              // owning lane: L1 + H, no bcast
            const int idx = ya & 7;
            float A = 0.0f, p = 0.0f;
            #pragma unroll
            for (int k = 0; k < 8; k++)
                if (k == idx) { A = offa + sa[k]; p = k ? sa[k]-sa[k-1] : sa[0]; }
            atomicAdd(&sL1, eva ? -__logf(p) : -__logf(1.0f - A));
            if (eva) atomicAdd(&sH[ya], exp_small(-A * SIGMA_INV));
        }
        if (eva) {
            #pragma unroll
            for (int k = 0; k < 8; k++) {
                float e = exp_small((offa + sa[k]) * SIGMA_INV);
                if (base + k < ya) acc[k] += e;
            }
        }
    }

    // ---- row B ----
    if (jb < N) {
        if (lane == (yb >> 3)) {
            const int idx = yb & 7;
            float A = 0.0f, p = 0.0f;
            #pragma unroll
            for (int k = 0; k < 8; k++)
                if (k == idx) { A = offb + sb[k]; p = k ? sb[k]-sb[k-1] : sb[0]; }
            atomicAdd(&sL1, evb ? -__logf(p) : -__logf(1.0f - A));
            if (evb) atomicAdd(&sH[yb], exp_small(-A * SIGMA_INV));
        }
        if (evb) {
            #pragma unroll
            for (int k = 0; k < 8; k++) {
                float e = exp_small((offb + sb[k]) * SIGMA_INV);
                if (base + k < yb) acc[k] += e;
            }
        }
    }

    // ---- generic fallback (not taken at N=8192 with this grid) ----
    for (int j = gw + 2 * W; j < N; j += W) {
        const float* r = yp + (size_t)j * TT + lane * 8;
        float4 c0 = *(const float4*)(r), c1 = *(const float4*)(r + 4);
        float s[8];
        s[0] = c0.x; s[1] = s[0]+c0.y; s[2] = s[1]+c0.z; s[3] = s[2]+c0.w;
        s[4] = s[3]+c1.x; s[5] = s[4]+c1.y; s[6] = s[5]+c1.z; s[7] = s[6]+c1.w;
        float tt0 = s[7], sc = tt0;
        #pragma unroll
        for (int o = 1; o < 32; o <<= 1) {
            float n = __shfl_up_sync(0xffffffffu, sc, o);
            if (lane >= o) sc += n;
        }
        float off = sc - tt0;
        int pj = 0;
        if (lane == 0)
            pj = (is64 ? y32[2*j] : y32[j]) | ((status[j] > 0.5f) ? 256 : 0);
        pj = __shfl_sync(0xffffffffu, pj, 0);
        const int yj = pj & 255; const bool ev = (pj & 256) != 0;
        if (lane == (yj >> 3)) {
            const int idx = yj & 7;
            float A = 0.0f, p = 0.0f;
            #pragma unroll
            for (int k = 0; k < 8; k++)
                if (k == idx) { A = off + s[k]; p = k ? s[k]-s[k-1] : s[0]; }
            atomicAdd(&sL1, ev ? -__logf(p) : -__logf(1.0f - A));
            if (ev) atomicAdd(&sH[yj], exp_small(-A * SIGMA_INV));
        }
        if (ev) {
            #pragma unroll
            for (int k = 0; k < 8; k++) {
                float e = exp_small((off + s[k]) * SIGMA_INV);
                if (base + k < yj) acc[k] += e;
            }
        }
    }

    // ---- block-level reduce: acc -> gS, sH -> gH, sL1 -> gL1 ----
    __shared__ float sRed[WPB][TT];
    #pragma unroll
    for (int k = 0; k < 8; k++) sRed[w][base + k] = acc[k];
    __syncthreads();
    {
        float colSum = 0.0f;
        #pragma unroll
        for (int ww = 0; ww < WPB; ww++) colSum += sRed[ww][t];
        if (colSum != 0.0f) atomicAdd(&gS[t], colSum);
        float h = sH[t];
        if (h != 0.0f) atomicAdd(&gH[t], h);
        if (t == 0) atomicAdd(&gL1, (double)sL1);
    }

    // ---- arrival counter: last block finalizes + resets ----
    __threadfence();
    __shared__ bool isLast;
    if (t == 0) {
        unsigned old = atomicAdd(&gCount, 1u);
        isLast = (old == (unsigned)(gridDim.x - 1));
    }
    __syncthreads();
    if (!isLast) return;

    // Finalize: L2 = sum_t gS[t] * gH[t]
    double d = (double)(__ldcg(&gS[t]) * __ldcg(&gH[t]));
    #pragma unroll
    for (int o = 16; o > 0; o >>= 1)
        d += __shfl_down_sync(0xffffffffu, d, o);
    __shared__ double sD[WPB];
    if (lane == 0) sD[w] = d;
    __syncthreads();
    if (t == 0) {
        double tot = 0.0;
        #pragma unroll
        for (int ww = 0; ww < WPB; ww++) tot += sD[ww];
        out[0] = (float)(gL1 + tot);
    }

    // reset for next graph replay
    __syncthreads();
    gS[t] = 0.0f;
    gH[t] = 0.0f;
    if (t == 0) { gL1 = 0.0; gCount = 0u; }
}

extern "C" void kernel_launch(void* const* d_in, const int* in_sizes, int n_in,
                              void* d_out, int out_size) {
    const float* y_pred = (const float*)d_in[0];
    const void*  y      = d_in[1];
    const float* status = (const float*)d_in[2];
    const int N = in_sizes[2];   // status length = N independent of y width
    surv_fused<<<BLOCKS, THREADS>>>(y_pred, y, status, N, (float*)d_out);
}

// round 17
// speedup vs baseline: 1.1572x; 1.1572x over previous
#include <cuda_runtime.h>
#include <cuda_bf16.h>

#define TT 256
#define SIGMA_INV (1.0f / 100.0f)
#define BLOCKS 304
#define THREADS 512
#define WPB 16                 // warps per block

// Scratch: device globals (allocation-free rule). Zero at module load; the
// LAST block re-zeros after consuming, so every graph replay sees clean state.
__device__ float        gS[TT];   // S[t] = sum_j ev_j [y_j > t] exp(F1[j,t]/s)
__device__ float        gH[TT];   // H[t] = sum_{i: y_i = t} ev_i exp(-A_i/s)
__device__ double       gL1;
__device__ unsigned int gCount;

// exp(x) for |x| <= 0.009 : cubic Taylor, rel err < 3e-10
__device__ __forceinline__ float exp_small(float x) {
    return fmaf(x, fmaf(x, fmaf(x, 0.16666667f, 0.5f), 1.0f), 1.0f);
}

__global__ void __launch_bounds__(THREADS, 2)
surv_fused(const float* __restrict__ yp,
           const void*  __restrict__ yv,
           const float* __restrict__ status,
           int N,
           float* __restrict__ out) {
    const int t    = threadIdx.x;
    const int lane = t & 31;
    const int w    = t >> 5;
    const int gw   = blockIdx.x * WPB + w;
    const int W    = gridDim.x * WPB;       // 4864 total warps
    const int* y32 = (const int*)yv;

    // ---- issue ALL independent global loads up front ----
    const int det = (2 * lane + 1 < N) ? y32[2 * lane + 1] : 0;

    const int ja = gw, jb = gw + W;          // this warp's two rows
    float4 xa0, xa1, xb0, xb1;
    if (ja < N) {
        const float* r = yp + (size_t)ja * TT + lane * 8;
        xa0 = *(const float4*)(r); xa1 = *(const float4*)(r + 4);
    }
    if (jb < N) {
        const float* r = yp + (size_t)jb * TT + lane * 8;
        xb0 = *(const float4*)(r); xb1 = *(const float4*)(r + 4);
    }

    // speculative metadata: int32 candidate (word j, in-bounds always) and
    // int64 candidate (word 2j, issued when 2j < N — in-bounds under both
    // width interpretations). Status loads are width-independent.
    int y32a = 0, y32b = 0, y64a = 0, y64b = 0;
    float sta = 0.0f, stb = 0.0f;
    if (lane == 0) {
        if (ja < N) {
            y32a = y32[ja];
            if (2 * ja < N) y64a = y32[2 * ja];
            sta = status[ja];
        }
        if (jb < N) {
            y32b = y32[jb];
            if (2 * jb < N) y64b = y32[2 * jb];
            stb = status[jb];
        }
    }

    // width detect (int64 LE: odd 32-bit words all zero since 0 <= y < 256)
    const bool is64 = (__ballot_sync(0xffffffffu, det != 0) == 0u);

    int pk = 0;
    if (lane == 0) {
        if (ja < N) {
            int ya = is64 ? ((2 * ja < N) ? y64a : y32[2 * ja]) : y32a;
            pk |= ya | ((sta > 0.5f) ? 256 : 0);
        }
        if (jb < N) {
            int yb = is64 ? ((2 * jb < N) ? y64b : y32[2 * jb]) : y32b;
            pk |= (yb << 16) | ((stb > 0.5f) ? (1 << 24) : 0);
        }
    }

    __shared__ float sH[TT];
    __shared__ float sL1;
    if (t < TT) sH[t] = 0.0f;
    if (t == THREADS - 1) sL1 = 0.0f;
    __syncthreads();                          // visible before loop atomics

    pk = __shfl_sync(0xffffffffu, pk, 0);     // one broadcast for both rows
    const int  ya  = pk & 255;
    const bool eva = (pk & 256) != 0;
    const int  yb  = (pk >> 16) & 255;
    const bool evb = (pk & (1 << 24)) != 0;

    float acc[8];
    #pragma unroll
    for (int k = 0; k < 8; k++) acc[k] = 0.0f;

    // ---- local inclusive prefixes (independent chains) ----
    float sa[8], sb[8];
    if (ja < N) {
        sa[0] = xa0.x; sa[1] = sa[0] + xa0.y; sa[2] = sa[1] + xa0.z;
        sa[3] = sa[2] + xa0.w; sa[4] = sa[3] + xa1.x; sa[5] = sa[4] + xa1.y;
        sa[6] = sa[5] + xa1.z; sa[7] = sa[6] + xa1.w;
    }
    if (jb < N) {
        sb[0] = xb0.x; sb[1] = sb[0] + xb0.y; sb[2] = sb[1] + xb0.z;
        sb[3] = sb[2] + xb0.w; sb[4] = sb[3] + xb1.x; sb[5] = sb[4] + xb1.y;
        sb[6] = sb[5] + xb1.z; sb[7] = sb[6] + xb1.w;
    }

    // ---- interleaved warp scans (latencies overlap) ----
    float ta = (ja < N) ? sa[7] : 0.0f;
    float tb = (jb < N) ? sb[7] : 0.0f;
    float sca = ta, scb = tb;
    #pragma unroll
    for (int o = 1; o < 32; o <<= 1) {
        float na = __shfl_up_sync(0xffffffffu, sca, o);
        float nb = __shfl_up_sync(0xffffffffu, scb, o);
        if (lane >= o) { sca += na; scb += nb; }
    }
    const float offa = sca - ta;
    const float offb = scb - tb;
    const int base = lane * 8;

    // ---- row A ----
    if (ja < N) {
        if (lane == (ya >> 3)) {              // owning lane: L1 + H, no bcast
            const int idx = ya & 7;
            float A = 0.0f, p = 0.0f;
            #pragma unroll
            for (int k = 0; k < 8; k++)
                if (k == idx) { A = offa + sa[k]; p = k ? sa[k]-sa[k-1] : sa[0]; }
            atomicAdd(&sL1, eva ? -__logf(p) : -__logf(1.0f - A));
            if (eva) atomicAdd(&sH[ya], exp_small(-A * SIGMA_INV));
        }
        if (eva) {
            #pragma unroll
            for (int k = 0; k < 8; k++) {
                float e = exp_small((offa + sa[k]) * SIGMA_INV);
                if (base + k < ya) acc[k] += e;
            }
        }
    }

    // ---- row B ----
    if (jb < N) {
        if (lane == (yb >> 3)) {
            const int idx = yb & 7;
            float A = 0.0f, p = 0.0f;
            #pragma unroll
            for (int k = 0; k < 8; k++)
                if (k == idx) { A = offb + sb[k]; p = k ? sb[k]-sb[k-1] : sb[0]; }
            atomicAdd(&sL1, evb ? -__logf(p) : -__logf(1.0f - A));
            if (evb) atomicAdd(&sH[yb], exp_small(-A * SIGMA_INV));
        }
        if (evb) {
            #pragma unroll
            for (int k = 0; k < 8; k++) {
                float e = exp_small((offb + sb[k]) * SIGMA_INV);
                if (base + k < yb) acc[k] += e;
            }
        }
    }

    // ---- generic fallback (not taken at N=8192 with this grid) ----
    for (int j = gw + 2 * W; j < N; j += W) {
        const float* r = yp + (size_t)j * TT + lane * 8;
        float4 c0 = *(const float4*)(r), c1 = *(const float4*)(r + 4);
        float s[8];
        s[0] = c0.x; s[1] = s[0]+c0.y; s[2] = s[1]+c0.z; s[3] = s[2]+c0.w;
        s[4] = s[3]+c1.x; s[5] = s[4]+c1.y; s[6] = s[5]+c1.z; s[7] = s[6]+c1.w;
        float tt0 = s[7], sc = tt0;
        #pragma unroll
        for (int o = 1; o < 32; o <<= 1) {
            float n = __shfl_up_sync(0xffffffffu, sc, o);
            if (lane >= o) sc += n;
        }
        float off = sc - tt0;
        int pj = 0;
        if (lane == 0)
            pj = (is64 ? y32[2*j] : y32[j]) | ((status[j] > 0.5f) ? 256 : 0);
        pj = __shfl_sync(0xffffffffu, pj, 0);
        const int yj = pj & 255; const bool ev = (pj & 256) != 0;
        if (lane == (yj >> 3)) {
            const int idx = yj & 7;
            float A = 0.0f, p = 0.0f;
            #pragma unroll
            for (int k = 0; k < 8; k++)
                if (k == idx) { A = off + s[k]; p = k ? s[k]-s[k-1] : s[0]; }
            atomicAdd(&sL1, ev ? -__logf(p) : -__logf(1.0f - A));
            if (ev) atomicAdd(&sH[yj], exp_small(-A * SIGMA_INV));
        }
        if (ev) {
            #pragma unroll
            for (int k = 0; k < 8; k++) {
                float e = exp_small((off + s[k]) * SIGMA_INV);
                if (base + k < yj) acc[k] += e;
            }
        }
    }

    // ---- block-level reduce: acc -> gS, sH -> gH, sL1 -> gL1 ----
    __shared__ float sRed[WPB][TT];
    #pragma unroll
    for (int k = 0; k < 8; k++) sRed[w][base + k] = acc[k];
    __syncthreads();
    if (t < TT) {
        float colSum = 0.0f;
        #pragma unroll
        for (int ww = 0; ww < WPB; ww++) colSum += sRed[ww][t];
        if (colSum != 0.0f) atomicAdd(&gS[t], colSum);
        float h = sH[t];
        if (h != 0.0f) atomicAdd(&gH[t], h);
        if (t == 0) atomicAdd(&gL1, (double)sL1);
    }

    // ---- arrival counter: last block finalizes + resets ----
    __threadfence();
    __shared__ bool isLast;
    if (t == 0) {
        unsigned old = atomicAdd(&gCount, 1u);
        isLast = (old == (unsigned)(gridDim.x - 1));
    }
    __syncthreads();
    if (!isLast) return;

    // Finalize: L2 = sum_t gS[t] * gH[t]
    double d = (t < TT) ? (double)(__ldcg(&gS[t]) * __ldcg(&gH[t])) : 0.0;
    #pragma unroll
    for (int o = 16; o > 0; o >>= 1)
        d += __shfl_down_sync(0xffffffffu, d, o);
    __shared__ double sD[WPB];
    if (lane == 0) sD[w] = d;
    __syncthreads();
    if (t == 0) {
        double tot = 0.0;
        #pragma unroll
        for (int ww = 0; ww < WPB; ww++) tot += sD[ww];
        out[0] = (float)(gL1 + tot);
    }

    // reset for next graph replay
    __syncthreads();
    if (t < TT) { gS[t] = 0.0f; gH[t] = 0.0f; }
    if (t == 0) { gL1 = 0.0; gCount = 0u; }
}

extern "C" void kernel_launch(void* const* d_in, const int* in_sizes, int n_in,
                              void* d_out, int out_size) {
    const float* y_pred = (const float*)d_in[0];
    const void*  y      = d_in[1];
    const float* status = (const float*)d_in[2];
    const int N = in_sizes[2];   // status length = N independent of y width
    surv_fused<<<BLOCKS, THREADS>>>(y_pred, y, status, N, (float*)d_out);
}